// round 16
// baseline (speedup 1.0000x reference)
#include <cuda_runtime.h>
#include <cuda_bf16.h>
#include <math.h>
#include <stdint.h>

#define BATCH  4
#define CH     256
#define NGROUP 32
#define HW     4096
#define GEPS   1e-6f
#define STAGES 3
#define STAGE_BYTES 32768u

typedef __nv_bfloat16 bf16;

// ---------------- scratch (device globals; no allocation allowed) -------------
__device__ bf16  g_ofT[(size_t)BATCH * HW * CH];   // GN output, transposed [b][i][c]
__device__ bf16  g_q  [(size_t)BATCH * HW * CH];   // Q  [b][i][c]
__device__ bf16  g_k  [(size_t)BATCH * HW * CH];   // K  [b][j][c]
__device__ bf16  g_v  [(size_t)BATCH * CH * HW];   // V  [b][c][j]
__device__ bf16  g_atT[(size_t)BATCH * HW * CH];   // attn out transposed [b][i][c]
__device__ bf16  g_s  [(size_t)BATCH * HW * HW];   // expS bf16 (134MB)
__device__ bf16  g_w16[4 * CH * CH];               // bf16 weights: wq|wk|wv|wp
__device__ float g_l  [BATCH * HW];                // softmax row sums (atomic)
__device__ float g_part[BATCH * NGROUP * 16];      // GN partials (slotted, no atomics)
__device__ int   g_cnt_s[BATCH * 32];              // scores->attn counters per (b, i-tile)
__device__ int   g_cnt_a[BATCH * 32];              // attn->proj counters per (b, i-tile)

// ---------------- prep: GN stats slices + weight conv + zero l/counters ---------
__global__ void __launch_bounds__(256) prep(const float* __restrict__ x,
                                            const float* __restrict__ wq,
                                            const float* __restrict__ wk,
                                            const float* __restrict__ wv,
                                            const float* __restrict__ wp) {
    const int blk = blockIdx.x;
    const int tid = threadIdx.x;

    if (blk < 1024) {
        const int bg = blk >> 3, slice = blk & 7;
        const float* p = x + (size_t)bg * (CH / NGROUP) * HW + (size_t)slice * 4096;

        float s = 0.f, s2 = 0.f;
        #pragma unroll
        for (int i = 0; i < 4; i++) {
            float4 v = ((const float4*)p)[tid + i * 256];
            s  += v.x + v.y + v.z + v.w;
            s2 += v.x * v.x + v.y * v.y + v.z * v.z + v.w * v.w;
        }
        __shared__ float red[64];
        #pragma unroll
        for (int o = 16; o; o >>= 1) {
            s  += __shfl_xor_sync(0xffffffffu, s,  o);
            s2 += __shfl_xor_sync(0xffffffffu, s2, o);
        }
        if ((tid & 31) == 0) { red[tid >> 5] = s; red[32 + (tid >> 5)] = s2; }
        __syncthreads();
        if (tid == 0) {
            float ts = 0.f, ts2 = 0.f;
            #pragma unroll
            for (int w = 0; w < 8; w++) { ts += red[w]; ts2 += red[32 + w]; }
            g_part[bg * 16 + slice]     = ts;
            g_part[bg * 16 + 8 + slice] = ts2;
        }
    } else {
        int i = (blk - 1024) * 256 + tid;            // 0..65535
        if (i < BATCH * HW) g_l[i] = 0.f;
        if (i < BATCH * 32) { g_cnt_s[i] = 0; g_cnt_a[i] = 0; }
        g_w16[0 * CH * CH + i] = __float2bfloat16_rn(wq[i]);
        g_w16[1 * CH * CH + i] = __float2bfloat16_rn(wk[i]);
        g_w16[2 * CH * CH + i] = __float2bfloat16_rn(wv[i]);
        g_w16[3 * CH * CH + i] = __float2bfloat16_rn(wp[i]);
    }
}

// ---------------- GroupNorm apply + transpose -> bf16 OF^T [b][i][c] -----------
__global__ void __launch_bounds__(256) gn_apply_t(const float* __restrict__ x,
                                                  const float* __restrict__ gs,
                                                  const float* __restrict__ gb) {
    __shared__ float tile[64][33];
    __shared__ float gmean[8], grstd[8];
    const int i0 = blockIdx.x * 32, c0 = blockIdx.y * 64, b = blockIdx.z;
    const int tid = threadIdx.x;
    const int il = tid & 31, cbase = tid >> 5;

    if (tid < 8) {
        const int bg = b * NGROUP + (c0 >> 3) + tid;
        float s = 0.f, s2 = 0.f;
        #pragma unroll
        for (int k = 0; k < 8; k++) { s += g_part[bg * 16 + k]; s2 += g_part[bg * 16 + 8 + k]; }
        const float inv_n = 1.0f / ((CH / NGROUP) * HW);
        float mean = s * inv_n;
        float var  = s2 * inv_n - mean * mean;
        gmean[tid] = mean;
        grstd[tid] = rsqrtf(var + GEPS);
    }
    __syncthreads();

    #pragma unroll
    for (int cc = 0; cc < 8; cc++) {
        int cl = cbase + cc * 8;
        int c = c0 + cl;
        int g = cl >> 3;
        float r = grstd[g];
        float a = gs[c] * r;
        float t = gb[c] - gmean[g] * a;
        float v = x[((size_t)b * CH + c) * HW + i0 + il];
        tile[cl][il] = v * a + t;
    }
    __syncthreads();

    #pragma unroll
    for (int h = 0; h < 4; h++) {
        int p = tid + h * 256;
        int ir = p >> 5, cl = (p & 31) * 2;
        __nv_bfloat162 o;
        o.x = __float2bfloat16_rn(tile[cl][ir]);
        o.y = __float2bfloat16_rn(tile[cl + 1][ir]);
        *(__nv_bfloat162*)(&g_ofT[((size_t)b * HW + i0 + ir) * CH + c0 + cl]) = o;
    }
}

// ---------------- GEMM body (mma.sync HMMA, shared by all launches) -------------
// D[m][n] = scale * sum_k A[m][k]*B[n][k]; A/B tile-offset, D/resid/lrow batch-offset.
// EPI 4: fp32 out + bias[m] + resid.   EPI 5: bf16 exp(acc*scale) + lrow atomics.
// EPI 6: bf16 acc / lrow[row].         EPI 8: bf16 + bias[n].   EPI 9: bf16 + bias[m].
// CTA 128x128, 8 warps (2m x 4n), BK=64/stage, STAGES=3, one sync per 64-K.

__device__ __forceinline__ unsigned swz(int m, int c) {
    return (unsigned)((m << 2) + (c ^ ((m >> 1) & 3)));
}

#define CP16(dst_u32, src_ptr) \
    asm volatile("cp.async.cg.shared.global [%0], [%1], 16;\n" :: "r"(dst_u32), "l"(src_ptr))
#define LDMX4(r0, r1, r2, r3, addr) \
    asm volatile("ldmatrix.sync.aligned.m8n8.x4.shared.b16 {%0,%1,%2,%3}, [%4];\n" \
                 : "=r"(r0), "=r"(r1), "=r"(r2), "=r"(r3) : "r"(addr))
#define MMA16816(c0, c1, c2, c3, a0, a1, a2, a3, b0, b1) \
    asm volatile("mma.sync.aligned.m16n8k16.row.col.f32.bf16.bf16.f32 " \
                 "{%0,%1,%2,%3}, {%4,%5,%6,%7}, {%8,%9}, {%0,%1,%2,%3};\n" \
                 : "+f"(c0), "+f"(c1), "+f"(c2), "+f"(c3) \
                 : "r"(a0), "r"(a1), "r"(a2), "r"(a3), "r"(b0), "r"(b1))
#define COMMIT() asm volatile("cp.async.commit_group;\n")
#define WAITG(n) asm volatile("cp.async.wait_group %0;\n" :: "n"(n))

#define GEMM_SMEM_BYTES (STAGES * STAGE_BYTES)

template<int EPI>
__device__ __forceinline__ void gemm_body(
    const bf16* __restrict__ Ap, const bf16* __restrict__ Bp,
    int K, int Nout, int m0, int n0, float scale,
    void* __restrict__ Dp, const float* __restrict__ bias,
    const float* __restrict__ resid, float* __restrict__ lrow)
{
    extern __shared__ __align__(16) unsigned char sm[];
    const int tid = threadIdx.x, lane = tid & 31, warp = tid >> 5;
    const int wm = warp >> 2, wn = warp & 3;

    const unsigned smbase = (unsigned)__cvta_generic_to_shared(sm);

    const int lm = tid >> 2, lc = tid & 3;
    const bf16* gA0 = Ap + (size_t)(lm)      * K + lc * 8;
    const bf16* gA1 = Ap + (size_t)(lm + 64) * K + lc * 8;
    const bf16* gB0 = Bp + (size_t)(lm)      * K + lc * 8;
    const bf16* gB1 = Bp + (size_t)(lm + 64) * K + lc * 8;
    const unsigned dA0 = swz(lm, lc) * 16u;
    const unsigned dA1 = swz(lm + 64, lc) * 16u;
    const unsigned dB0 = 8192u + swz(lm, lc) * 16u;
    const unsigned dB1 = 8192u + swz(lm + 64, lc) * 16u;

    unsigned aOff[4], bOff[2];
    {
        int r = wm * 64 + (lane & 15);
        int c0 = lane >> 4;
        #pragma unroll
        for (int mt = 0; mt < 4; mt++) aOff[mt] = swz(r + mt * 16, c0) * 16u;
    }
    {
        int r = wn * 32 + ((lane >> 4) << 3) + (lane & 7);
        int c0 = (lane >> 3) & 1;
        #pragma unroll
        for (int p = 0; p < 2; p++) bOff[p] = 8192u + swz(r + p * 16, c0) * 16u;
    }

    float acc[4][4][4];
    #pragma unroll
    for (int i = 0; i < 4; i++)
        #pragma unroll
        for (int j = 0; j < 4; j++)
            #pragma unroll
            for (int r = 0; r < 4; r++) acc[i][j][r] = 0.f;

    const int iters = K >> 6;

    #pragma unroll
    for (int s = 0; s < STAGES - 1; ++s) {
        unsigned st = smbase + (unsigned)s * STAGE_BYTES;
        #pragma unroll
        for (int sub = 0; sub < 2; ++sub) {
            unsigned sp = st + (unsigned)sub * 16384u;
            int k0 = (s * 2 + sub) << 5;
            CP16(sp + dA0, gA0 + k0); CP16(sp + dA1, gA1 + k0);
            CP16(sp + dB0, gB0 + k0); CP16(sp + dB1, gB1 + k0);
        }
        COMMIT();
    }

    int cs = 0;
    for (int it = 0; it < iters; ++it) {
        WAITG(STAGES - 2);
        __syncthreads();
        {
            int pf = it + STAGES - 1;
            if (pf < iters) {
                int fs = cs - 1; if (fs < 0) fs = STAGES - 1;
                unsigned st = smbase + (unsigned)fs * STAGE_BYTES;
                #pragma unroll
                for (int sub = 0; sub < 2; ++sub) {
                    unsigned sp = st + (unsigned)sub * 16384u;
                    int k0 = (pf * 2 + sub) << 5;
                    CP16(sp + dA0, gA0 + k0); CP16(sp + dA1, gA1 + k0);
                    CP16(sp + dB0, gB0 + k0); CP16(sp + dB1, gB1 + k0);
                }
            }
            COMMIT();
        }

        const unsigned sb0 = smbase + (unsigned)cs * STAGE_BYTES;
        #pragma unroll
        for (int sub = 0; sub < 2; ++sub) {
            const unsigned sb = sb0 + (unsigned)sub * 16384u;
            #pragma unroll
            for (int ks = 0; ks < 2; ++ks) {
                const unsigned kx = (unsigned)ks * 32u;
                unsigned a[4][4], b[2][4];
                #pragma unroll
                for (int mt = 0; mt < 4; mt++)
                    LDMX4(a[mt][0], a[mt][1], a[mt][2], a[mt][3], sb + (aOff[mt] ^ kx));
                #pragma unroll
                for (int p = 0; p < 2; p++)
                    LDMX4(b[p][0], b[p][1], b[p][2], b[p][3], sb + (bOff[p] ^ kx));

                #pragma unroll
                for (int mt = 0; mt < 4; mt++) {
                    #pragma unroll
                    for (int nt = 0; nt < 4; nt++) {
                        const int p = nt >> 1, h = (nt & 1) << 1;
                        MMA16816(acc[mt][nt][0], acc[mt][nt][1], acc[mt][nt][2], acc[mt][nt][3],
                                 a[mt][0], a[mt][1], a[mt][2], a[mt][3],
                                 b[p][h + 0], b[p][h + 1]);
                    }
                }
            }
        }
        if (++cs == STAGES) cs = 0;
    }

    const int row = m0 + wm * 64 + (lane >> 2);
    const int col = n0 + wn * 32 + (lane & 3) * 2;

    if (EPI == 4) {
        float* D = (float*)Dp;
        #pragma unroll
        for (int mt = 0; mt < 4; mt++) {
            #pragma unroll
            for (int nt = 0; nt < 4; nt++) {
                int r = row + mt * 16, cc = col + nt * 8;
                float b0 = bias[r], b1 = bias[r + 8];
                float2 v0 = { acc[mt][nt][0] + b0, acc[mt][nt][1] + b0 };
                float2 v1 = { acc[mt][nt][2] + b1, acc[mt][nt][3] + b1 };
                float2 r0 = *(const float2*)(&resid[(size_t)r * Nout + cc]);
                float2 r1 = *(const float2*)(&resid[(size_t)(r + 8) * Nout + cc]);
                v0.x += r0.x; v0.y += r0.y; v1.x += r1.x; v1.y += r1.y;
                *(float2*)(&D[(size_t)r * Nout + cc])       = v0;
                *(float2*)(&D[(size_t)(r + 8) * Nout + cc]) = v1;
            }
        }
    } else if (EPI == 5) {
        bf16* D = (bf16*)Dp;
        #pragma unroll
        for (int mt = 0; mt < 4; mt++) {
            const int r = row + mt * 16;
            float s0 = 0.f, s1 = 0.f;
            #pragma unroll
            for (int nt = 0; nt < 4; nt++) {
                int cc = col + nt * 8;
                float e0 = __expf(acc[mt][nt][0] * scale);
                float e1 = __expf(acc[mt][nt][1] * scale);
                float e2 = __expf(acc[mt][nt][2] * scale);
                float e3 = __expf(acc[mt][nt][3] * scale);
                s0 += e0 + e1;  s1 += e2 + e3;
                __nv_bfloat162 o0 = __floats2bfloat162_rn(e0, e1);
                __nv_bfloat162 o1 = __floats2bfloat162_rn(e2, e3);
                *(__nv_bfloat162*)(&D[(size_t)r * Nout + cc])       = o0;
                *(__nv_bfloat162*)(&D[(size_t)(r + 8) * Nout + cc]) = o1;
            }
            s0 += __shfl_xor_sync(0xffffffffu, s0, 1);
            s0 += __shfl_xor_sync(0xffffffffu, s0, 2);
            s1 += __shfl_xor_sync(0xffffffffu, s1, 1);
            s1 += __shfl_xor_sync(0xffffffffu, s1, 2);
            if ((lane & 3) == 0) {
                atomicAdd(&lrow[r],     s0);
                atomicAdd(&lrow[r + 8], s1);
            }
        }
    } else if (EPI == 6) {
        bf16* D = (bf16*)Dp;
        #pragma unroll
        for (int mt = 0; mt < 4; mt++) {
            const int r = row + mt * 16;
            const float inv0 = 1.0f / lrow[r];
            const float inv1 = 1.0f / lrow[r + 8];
            #pragma unroll
            for (int nt = 0; nt < 4; nt++) {
                int cc = col + nt * 8;
                __nv_bfloat162 o0 = __floats2bfloat162_rn(acc[mt][nt][0] * inv0,
                                                          acc[mt][nt][1] * inv0);
                __nv_bfloat162 o1 = __floats2bfloat162_rn(acc[mt][nt][2] * inv1,
                                                          acc[mt][nt][3] * inv1);
                *(__nv_bfloat162*)(&D[(size_t)r * Nout + cc])       = o0;
                *(__nv_bfloat162*)(&D[(size_t)(r + 8) * Nout + cc]) = o1;
            }
        }
    } else {
        bf16* D = (bf16*)Dp;
        #pragma unroll
        for (int mt = 0; mt < 4; mt++) {
            #pragma unroll
            for (int nt = 0; nt < 4; nt++) {
                int r = row + mt * 16, cc = col + nt * 8;
                float ax, ay, bx, by;
                if (EPI == 9) {
                    float t0 = bias[r], t1 = bias[r + 8];
                    ax = t0; ay = t0; bx = t1; by = t1;
                } else {
                    float t0 = bias[cc], t1 = bias[cc + 1];
                    ax = t0; ay = t1; bx = t0; by = t1;
                }
                __nv_bfloat162 o0, o1;
                o0.x = __float2bfloat16_rn(acc[mt][nt][0] + ax);
                o0.y = __float2bfloat16_rn(acc[mt][nt][1] + ay);
                o1.x = __float2bfloat16_rn(acc[mt][nt][2] + bx);
                o1.y = __float2bfloat16_rn(acc[mt][nt][3] + by);
                *(__nv_bfloat162*)(&D[(size_t)r * Nout + cc])       = o0;
                *(__nv_bfloat162*)(&D[(size_t)(r + 8) * Nout + cc]) = o1;
            }
        }
    }
}

// ---------------- QKV: one launch, grid (6, 32, 4) ------------------------------
__global__ void __launch_bounds__(256, 2) qkv_kernel(
    const float* __restrict__ bq, const float* __restrict__ bk,
    const float* __restrict__ bv)
{
    const int bz = blockIdx.z;
    if (blockIdx.x < 4) {
        const bf16* Ap = g_ofT + (size_t)bz * CH * HW + (size_t)(blockIdx.y * 128) * CH;
        const bf16* Bp = g_w16 + (size_t)(blockIdx.x * 128) * CH;
        bf16* D = ((blockIdx.x >> 1) ? g_k : g_q) + (size_t)bz * CH * HW;
        gemm_body<8>(Ap, Bp, CH, CH, blockIdx.y * 128, (blockIdx.x & 1) * 128, 1.0f,
                     D, (blockIdx.x >> 1) ? bk : bq, nullptr, nullptr);
    } else {
        const bf16* Ap = g_w16 + 2 * CH * CH + (size_t)((blockIdx.x - 4) * 128) * CH;
        const bf16* Bp = g_ofT + (size_t)bz * CH * HW + (size_t)(blockIdx.y * 128) * CH;
        gemm_body<9>(Ap, Bp, CH, HW, (blockIdx.x - 4) * 128, blockIdx.y * 128, 1.0f,
                     g_v + (size_t)bz * CH * HW, bv, nullptr, nullptr);
    }
}

// ---------------- fused scores + attn + proj (counter-chained) ------------------
// bids 0..4095: scores (b=bid>>10, i-tile=(bid&1023)>>5, j-tile=bid&31)
// bids 4096..4351: attn (waits cnt_s[b][i]==32)
// bids 4352..4607: proj (waits cnt_a[b][i]==2) -> d_out
__global__ void __launch_bounds__(256, 2) fused_spa(
    float* __restrict__ out, const float* __restrict__ x,
    const float* __restrict__ bp)
{
    const int bid = blockIdx.x;
    const int tid = threadIdx.x;

    if (bid < 4096) {
        const int b = bid >> 10, r = bid & 1023, it = r >> 5, jt = r & 31;
        const bf16* Ap = g_q + (size_t)b * CH * HW + (size_t)(it * 128) * CH;
        const bf16* Bp = g_k + (size_t)b * CH * HW + (size_t)(jt * 128) * CH;
        gemm_body<5>(Ap, Bp, CH, HW, it * 128, jt * 128, 0.0625f,
                     g_s + (size_t)b * HW * HW, nullptr, nullptr, g_l + b * HW);
        __threadfence();
        __syncthreads();
        if (tid == 0) atomicAdd(&g_cnt_s[b * 32 + it], 1);
    } else if (bid < 4352) {
        const int t = bid - 4096, b = t >> 6, r = t & 63, it = r >> 1, ct = r & 1;
        if (tid == 0) {
            while (((volatile int*)g_cnt_s)[b * 32 + it] < 32) __nanosleep(128);
        }
        __syncthreads();
        const bf16* Ap = g_s + (size_t)b * HW * HW + (size_t)(it * 128) * HW;
        const bf16* Bp = g_v + (size_t)b * CH * HW + (size_t)(ct * 128) * HW;
        gemm_body<6>(Ap, Bp, HW, CH, it * 128, ct * 128, 1.0f,
                     g_atT + (size_t)b * CH * HW, nullptr, nullptr, g_l + b * HW);
        __threadfence();
        __syncthreads();
        if (tid == 0) atomicAdd(&g_cnt_a[b * 32 + it], 1);
    } else {
        const int t = bid - 4352, b = t >> 6, r = t & 63, it = r >> 1, ct = r & 1;
        if (tid == 0) {
            while (((volatile int*)g_cnt_a)[b * 32 + it] < 2) __nanosleep(128);
        }
        __syncthreads();
        const bf16* Ap = g_w16 + 3 * CH * CH + (size_t)(ct * 128) * CH;
        const bf16* Bp = g_atT + (size_t)b * CH * HW + (size_t)(it * 128) * CH;
        gemm_body<4>(Ap, Bp, CH, HW, ct * 128, it * 128, 1.0f,
                     out + (size_t)b * CH * HW, bp, x + (size_t)b * CH * HW, nullptr);
    }
}

// ---------------- launch --------------------------------------------------------
extern "C" void kernel_launch(void* const* d_in, const int* in_sizes, int n_in,
                              void* d_out, int out_size) {
    const float* x  = (const float*)d_in[0];
    const float* gs = (const float*)d_in[1];
    const float* gb = (const float*)d_in[2];
    const float* wq = (const float*)d_in[3];
    const float* bq = (const float*)d_in[4];
    const float* wk = (const float*)d_in[5];
    const float* bk = (const float*)d_in[6];
    const float* wv = (const float*)d_in[7];
    const float* bv = (const float*)d_in[8];
    const float* wp = (const float*)d_in[9];
    const float* bp = (const float*)d_in[10];
    float* out = (float*)d_out;

    cudaFuncSetAttribute(qkv_kernel, cudaFuncAttributeMaxDynamicSharedMemorySize, GEMM_SMEM_BYTES);
    cudaFuncSetAttribute(fused_spa,  cudaFuncAttributeMaxDynamicSharedMemorySize, GEMM_SMEM_BYTES);

    // 1) prep (stats slices + weight conv + zero l/counters) -> gn_apply_t
    prep<<<1280, 256>>>(x, wq, wk, wv, wp);
    gn_apply_t<<<dim3(HW / 32, CH / 64, BATCH), 256>>>(x, gs, gb);

    // 2) Q, K, V in one launch
    qkv_kernel<<<dim3(6, HW / 128, BATCH), 256, GEMM_SMEM_BYTES>>>(bq, bk, bv);

    // 3) scores + softmax + attn + proj in ONE counter-chained launch
    fused_spa<<<4608, 256, GEMM_SMEM_BYTES>>>(out, x, bp);
}

// round 17
// speedup vs baseline: 1.0170x; 1.0170x over previous
#include <cuda_runtime.h>
#include <cuda_bf16.h>
#include <math.h>
#include <stdint.h>

#define BATCH  4
#define CH     256
#define NGROUP 32
#define HW     4096
#define GEPS   1e-6f
#define STAGES 3
#define STAGE_BYTES 32768u

typedef __nv_bfloat16 bf16;

// ---------------- scratch (device globals; no allocation allowed) -------------
__device__ bf16  g_ofT[(size_t)BATCH * HW * CH];   // GN output, transposed [b][i][c]
__device__ bf16  g_q  [(size_t)BATCH * HW * CH];   // Q  [b][i][c]
__device__ bf16  g_k  [(size_t)BATCH * HW * CH];   // K  [b][j][c]
__device__ bf16  g_v  [(size_t)BATCH * CH * HW];   // V  [b][c][j]
__device__ bf16  g_atT[(size_t)BATCH * HW * CH];   // attn out transposed [b][i][c]
__device__ bf16  g_s  [(size_t)BATCH * HW * HW];   // expS bf16 (134MB)
__device__ bf16  g_w16[4 * CH * CH];               // bf16 weights: wq|wk|wv|wp
__device__ float g_l  [BATCH * HW];                // softmax row sums (atomic)
__device__ float g_part[BATCH * NGROUP * 16];      // GN partials (slotted, no atomics)
__device__ int   g_cnt[BATCH * 32];                // attn->proj counters per (b, i-tile)

// ---------------- prep: GN stats slices + weight conv + zero l/counters ---------
__global__ void __launch_bounds__(256) prep(const float* __restrict__ x,
                                            const float* __restrict__ wq,
                                            const float* __restrict__ wk,
                                            const float* __restrict__ wv,
                                            const float* __restrict__ wp) {
    const int blk = blockIdx.x;
    const int tid = threadIdx.x;

    if (blk < 1024) {
        const int bg = blk >> 3, slice = blk & 7;
        const float* p = x + (size_t)bg * (CH / NGROUP) * HW + (size_t)slice * 4096;

        float s = 0.f, s2 = 0.f;
        #pragma unroll
        for (int i = 0; i < 4; i++) {
            float4 v = ((const float4*)p)[tid + i * 256];
            s  += v.x + v.y + v.z + v.w;
            s2 += v.x * v.x + v.y * v.y + v.z * v.z + v.w * v.w;
        }
        __shared__ float red[64];
        #pragma unroll
        for (int o = 16; o; o >>= 1) {
            s  += __shfl_xor_sync(0xffffffffu, s,  o);
            s2 += __shfl_xor_sync(0xffffffffu, s2, o);
        }
        if ((tid & 31) == 0) { red[tid >> 5] = s; red[32 + (tid >> 5)] = s2; }
        __syncthreads();
        if (tid == 0) {
            float ts = 0.f, ts2 = 0.f;
            #pragma unroll
            for (int w = 0; w < 8; w++) { ts += red[w]; ts2 += red[32 + w]; }
            g_part[bg * 16 + slice]     = ts;
            g_part[bg * 16 + 8 + slice] = ts2;
        }
    } else {
        int i = (blk - 1024) * 256 + tid;            // 0..65535
        if (i < BATCH * HW) g_l[i] = 0.f;
        if (i < BATCH * 32) g_cnt[i] = 0;
        g_w16[0 * CH * CH + i] = __float2bfloat16_rn(wq[i]);
        g_w16[1 * CH * CH + i] = __float2bfloat16_rn(wk[i]);
        g_w16[2 * CH * CH + i] = __float2bfloat16_rn(wv[i]);
        g_w16[3 * CH * CH + i] = __float2bfloat16_rn(wp[i]);
    }
}

// ---------------- GroupNorm apply + transpose -> bf16 OF^T [b][i][c] -----------
__global__ void __launch_bounds__(256) gn_apply_t(const float* __restrict__ x,
                                                  const float* __restrict__ gs,
                                                  const float* __restrict__ gb) {
    __shared__ float tile[64][33];
    __shared__ float gmean[8], grstd[8];
    const int i0 = blockIdx.x * 32, c0 = blockIdx.y * 64, b = blockIdx.z;
    const int tid = threadIdx.x;
    const int il = tid & 31, cbase = tid >> 5;

    if (tid < 8) {
        const int bg = b * NGROUP + (c0 >> 3) + tid;
        float s = 0.f, s2 = 0.f;
        #pragma unroll
        for (int k = 0; k < 8; k++) { s += g_part[bg * 16 + k]; s2 += g_part[bg * 16 + 8 + k]; }
        const float inv_n = 1.0f / ((CH / NGROUP) * HW);
        float mean = s * inv_n;
        float var  = s2 * inv_n - mean * mean;
        gmean[tid] = mean;
        grstd[tid] = rsqrtf(var + GEPS);
    }
    __syncthreads();

    #pragma unroll
    for (int cc = 0; cc < 8; cc++) {
        int cl = cbase + cc * 8;
        int c = c0 + cl;
        int g = cl >> 3;
        float r = grstd[g];
        float a = gs[c] * r;
        float t = gb[c] - gmean[g] * a;
        float v = x[((size_t)b * CH + c) * HW + i0 + il];
        tile[cl][il] = v * a + t;
    }
    __syncthreads();

    #pragma unroll
    for (int h = 0; h < 4; h++) {
        int p = tid + h * 256;
        int ir = p >> 5, cl = (p & 31) * 2;
        __nv_bfloat162 o;
        o.x = __float2bfloat16_rn(tile[cl][ir]);
        o.y = __float2bfloat16_rn(tile[cl + 1][ir]);
        *(__nv_bfloat162*)(&g_ofT[((size_t)b * HW + i0 + ir) * CH + c0 + cl]) = o;
    }
}

// ---------------- GEMM body (mma.sync HMMA, shared by all launches) -------------
// D[m][n] = scale * sum_k A[m][k]*B[n][k]; A/B tile-offset, D/resid/lrow batch-offset.
// EPI 4: fp32 out + bias[m] + resid.   EPI 5: bf16 exp(acc*scale) + lrow atomics.
// EPI 6: bf16 acc / lrow[row].         EPI 8: bf16 + bias[n].   EPI 9: bf16 + bias[m].
// CTA 128x128, 8 warps (2m x 4n), BK=64/stage, STAGES=3, one sync per 64-K.

__device__ __forceinline__ unsigned swz(int m, int c) {
    return (unsigned)((m << 2) + (c ^ ((m >> 1) & 3)));
}

#define CP16(dst_u32, src_ptr) \
    asm volatile("cp.async.cg.shared.global [%0], [%1], 16;\n" :: "r"(dst_u32), "l"(src_ptr))
#define LDMX4(r0, r1, r2, r3, addr) \
    asm volatile("ldmatrix.sync.aligned.m8n8.x4.shared.b16 {%0,%1,%2,%3}, [%4];\n" \
                 : "=r"(r0), "=r"(r1), "=r"(r2), "=r"(r3) : "r"(addr))
#define MMA16816(c0, c1, c2, c3, a0, a1, a2, a3, b0, b1) \
    asm volatile("mma.sync.aligned.m16n8k16.row.col.f32.bf16.bf16.f32 " \
                 "{%0,%1,%2,%3}, {%4,%5,%6,%7}, {%8,%9}, {%0,%1,%2,%3};\n" \
                 : "+f"(c0), "+f"(c1), "+f"(c2), "+f"(c3) \
                 : "r"(a0), "r"(a1), "r"(a2), "r"(a3), "r"(b0), "r"(b1))
#define COMMIT() asm volatile("cp.async.commit_group;\n")
#define WAITG(n) asm volatile("cp.async.wait_group %0;\n" :: "n"(n))

#define GEMM_SMEM_BYTES (STAGES * STAGE_BYTES)

template<int EPI>
__device__ __forceinline__ void gemm_body(
    const bf16* __restrict__ Ap, const bf16* __restrict__ Bp,
    int K, int Nout, int m0, int n0, float scale,
    void* __restrict__ Dp, const float* __restrict__ bias,
    const float* __restrict__ resid, float* __restrict__ lrow)
{
    extern __shared__ __align__(16) unsigned char sm[];
    const int tid = threadIdx.x, lane = tid & 31, warp = tid >> 5;
    const int wm = warp >> 2, wn = warp & 3;

    const unsigned smbase = (unsigned)__cvta_generic_to_shared(sm);

    const int lm = tid >> 2, lc = tid & 3;
    const bf16* gA0 = Ap + (size_t)(lm)      * K + lc * 8;
    const bf16* gA1 = Ap + (size_t)(lm + 64) * K + lc * 8;
    const bf16* gB0 = Bp + (size_t)(lm)      * K + lc * 8;
    const bf16* gB1 = Bp + (size_t)(lm + 64) * K + lc * 8;
    const unsigned dA0 = swz(lm, lc) * 16u;
    const unsigned dA1 = swz(lm + 64, lc) * 16u;
    const unsigned dB0 = 8192u + swz(lm, lc) * 16u;
    const unsigned dB1 = 8192u + swz(lm + 64, lc) * 16u;

    unsigned aOff[4], bOff[2];
    {
        int r = wm * 64 + (lane & 15);
        int c0 = lane >> 4;
        #pragma unroll
        for (int mt = 0; mt < 4; mt++) aOff[mt] = swz(r + mt * 16, c0) * 16u;
    }
    {
        int r = wn * 32 + ((lane >> 4) << 3) + (lane & 7);
        int c0 = (lane >> 3) & 1;
        #pragma unroll
        for (int p = 0; p < 2; p++) bOff[p] = 8192u + swz(r + p * 16, c0) * 16u;
    }

    float acc[4][4][4];
    #pragma unroll
    for (int i = 0; i < 4; i++)
        #pragma unroll
        for (int j = 0; j < 4; j++)
            #pragma unroll
            for (int r = 0; r < 4; r++) acc[i][j][r] = 0.f;

    const int iters = K >> 6;

    #pragma unroll
    for (int s = 0; s < STAGES - 1; ++s) {
        unsigned st = smbase + (unsigned)s * STAGE_BYTES;
        #pragma unroll
        for (int sub = 0; sub < 2; ++sub) {
            unsigned sp = st + (unsigned)sub * 16384u;
            int k0 = (s * 2 + sub) << 5;
            CP16(sp + dA0, gA0 + k0); CP16(sp + dA1, gA1 + k0);
            CP16(sp + dB0, gB0 + k0); CP16(sp + dB1, gB1 + k0);
        }
        COMMIT();
    }

    int cs = 0;
    for (int it = 0; it < iters; ++it) {
        WAITG(STAGES - 2);
        __syncthreads();
        {
            int pf = it + STAGES - 1;
            if (pf < iters) {
                int fs = cs - 1; if (fs < 0) fs = STAGES - 1;
                unsigned st = smbase + (unsigned)fs * STAGE_BYTES;
                #pragma unroll
                for (int sub = 0; sub < 2; ++sub) {
                    unsigned sp = st + (unsigned)sub * 16384u;
                    int k0 = (pf * 2 + sub) << 5;
                    CP16(sp + dA0, gA0 + k0); CP16(sp + dA1, gA1 + k0);
                    CP16(sp + dB0, gB0 + k0); CP16(sp + dB1, gB1 + k0);
                }
            }
            COMMIT();
        }

        const unsigned sb0 = smbase + (unsigned)cs * STAGE_BYTES;
        #pragma unroll
        for (int sub = 0; sub < 2; ++sub) {
            const unsigned sb = sb0 + (unsigned)sub * 16384u;
            #pragma unroll
            for (int ks = 0; ks < 2; ++ks) {
                const unsigned kx = (unsigned)ks * 32u;
                unsigned a[4][4], b[2][4];
                #pragma unroll
                for (int mt = 0; mt < 4; mt++)
                    LDMX4(a[mt][0], a[mt][1], a[mt][2], a[mt][3], sb + (aOff[mt] ^ kx));
                #pragma unroll
                for (int p = 0; p < 2; p++)
                    LDMX4(b[p][0], b[p][1], b[p][2], b[p][3], sb + (bOff[p] ^ kx));

                #pragma unroll
                for (int mt = 0; mt < 4; mt++) {
                    #pragma unroll
                    for (int nt = 0; nt < 4; nt++) {
                        const int p = nt >> 1, h = (nt & 1) << 1;
                        MMA16816(acc[mt][nt][0], acc[mt][nt][1], acc[mt][nt][2], acc[mt][nt][3],
                                 a[mt][0], a[mt][1], a[mt][2], a[mt][3],
                                 b[p][h + 0], b[p][h + 1]);
                    }
                }
            }
        }
        if (++cs == STAGES) cs = 0;
    }

    const int row = m0 + wm * 64 + (lane >> 2);
    const int col = n0 + wn * 32 + (lane & 3) * 2;

    if (EPI == 4) {
        float* D = (float*)Dp;
        #pragma unroll
        for (int mt = 0; mt < 4; mt++) {
            #pragma unroll
            for (int nt = 0; nt < 4; nt++) {
                int r = row + mt * 16, cc = col + nt * 8;
                float b0 = bias[r], b1 = bias[r + 8];
                float2 v0 = { acc[mt][nt][0] + b0, acc[mt][nt][1] + b0 };
                float2 v1 = { acc[mt][nt][2] + b1, acc[mt][nt][3] + b1 };
                float2 r0 = *(const float2*)(&resid[(size_t)r * Nout + cc]);
                float2 r1 = *(const float2*)(&resid[(size_t)(r + 8) * Nout + cc]);
                v0.x += r0.x; v0.y += r0.y; v1.x += r1.x; v1.y += r1.y;
                *(float2*)(&D[(size_t)r * Nout + cc])       = v0;
                *(float2*)(&D[(size_t)(r + 8) * Nout + cc]) = v1;
            }
        }
    } else if (EPI == 5) {
        bf16* D = (bf16*)Dp;
        #pragma unroll
        for (int mt = 0; mt < 4; mt++) {
            const int r = row + mt * 16;
            float s0 = 0.f, s1 = 0.f;
            #pragma unroll
            for (int nt = 0; nt < 4; nt++) {
                int cc = col + nt * 8;
                float e0 = __expf(acc[mt][nt][0] * scale);
                float e1 = __expf(acc[mt][nt][1] * scale);
                float e2 = __expf(acc[mt][nt][2] * scale);
                float e3 = __expf(acc[mt][nt][3] * scale);
                s0 += e0 + e1;  s1 += e2 + e3;
                __nv_bfloat162 o0 = __floats2bfloat162_rn(e0, e1);
                __nv_bfloat162 o1 = __floats2bfloat162_rn(e2, e3);
                *(__nv_bfloat162*)(&D[(size_t)r * Nout + cc])       = o0;
                *(__nv_bfloat162*)(&D[(size_t)(r + 8) * Nout + cc]) = o1;
            }
            s0 += __shfl_xor_sync(0xffffffffu, s0, 1);
            s0 += __shfl_xor_sync(0xffffffffu, s0, 2);
            s1 += __shfl_xor_sync(0xffffffffu, s1, 1);
            s1 += __shfl_xor_sync(0xffffffffu, s1, 2);
            if ((lane & 3) == 0) {
                atomicAdd(&lrow[r],     s0);
                atomicAdd(&lrow[r + 8], s1);
            }
        }
    } else if (EPI == 6) {
        bf16* D = (bf16*)Dp;
        #pragma unroll
        for (int mt = 0; mt < 4; mt++) {
            const int r = row + mt * 16;
            const float inv0 = 1.0f / lrow[r];
            const float inv1 = 1.0f / lrow[r + 8];
            #pragma unroll
            for (int nt = 0; nt < 4; nt++) {
                int cc = col + nt * 8;
                __nv_bfloat162 o0 = __floats2bfloat162_rn(acc[mt][nt][0] * inv0,
                                                          acc[mt][nt][1] * inv0);
                __nv_bfloat162 o1 = __floats2bfloat162_rn(acc[mt][nt][2] * inv1,
                                                          acc[mt][nt][3] * inv1);
                *(__nv_bfloat162*)(&D[(size_t)r * Nout + cc])       = o0;
                *(__nv_bfloat162*)(&D[(size_t)(r + 8) * Nout + cc]) = o1;
            }
        }
    } else {
        bf16* D = (bf16*)Dp;
        #pragma unroll
        for (int mt = 0; mt < 4; mt++) {
            #pragma unroll
            for (int nt = 0; nt < 4; nt++) {
                int r = row + mt * 16, cc = col + nt * 8;
                float ax, ay, bx, by;
                if (EPI == 9) {
                    float t0 = bias[r], t1 = bias[r + 8];
                    ax = t0; ay = t0; bx = t1; by = t1;
                } else {
                    float t0 = bias[cc], t1 = bias[cc + 1];
                    ax = t0; ay = t1; bx = t0; by = t1;
                }
                __nv_bfloat162 o0, o1;
                o0.x = __float2bfloat16_rn(acc[mt][nt][0] + ax);
                o0.y = __float2bfloat16_rn(acc[mt][nt][1] + ay);
                o1.x = __float2bfloat16_rn(acc[mt][nt][2] + bx);
                o1.y = __float2bfloat16_rn(acc[mt][nt][3] + by);
                *(__nv_bfloat162*)(&D[(size_t)r * Nout + cc])       = o0;
                *(__nv_bfloat162*)(&D[(size_t)(r + 8) * Nout + cc]) = o1;
            }
        }
    }
}

// ---------------- QK: grid (4, 32, 4) -------------------------------------------
__global__ void __launch_bounds__(256, 2) qk_kernel(
    const float* __restrict__ bq, const float* __restrict__ bk)
{
    const int bz = blockIdx.z;
    const bf16* Ap = g_ofT + (size_t)bz * CH * HW + (size_t)(blockIdx.y * 128) * CH;
    const bf16* Bp = g_w16 + (size_t)(blockIdx.x * 128) * CH;
    bf16* D = ((blockIdx.x >> 1) ? g_k : g_q) + (size_t)bz * CH * HW;
    gemm_body<8>(Ap, Bp, CH, CH, blockIdx.y * 128, (blockIdx.x & 1) * 128, 1.0f,
                 D, (blockIdx.x >> 1) ? bk : bq, nullptr, nullptr);
}

// ---------------- V (independent) + scores in one launch -------------------------
// bids 0..255: V tiles (depend only on ofT). bids 256..4351: scores (need Q,K done
// before launch -- guaranteed by stream order).
__global__ void __launch_bounds__(256, 2) scores_v(const float* __restrict__ bv)
{
    const int bid = blockIdx.x;
    if (bid < 256) {
        const int b = bid >> 6, r = bid & 63, ct = r >> 5, jt = r & 31;
        const bf16* Ap = g_w16 + 2 * CH * CH + (size_t)(ct * 128) * CH;
        const bf16* Bp = g_ofT + (size_t)b * CH * HW + (size_t)(jt * 128) * CH;
        gemm_body<9>(Ap, Bp, CH, HW, ct * 128, jt * 128, 1.0f,
                     g_v + (size_t)b * CH * HW, bv, nullptr, nullptr);
    } else {
        const int s = bid - 256;
        const int b = s >> 10, r = s & 1023, it = r >> 5, jt = r & 31;
        const bf16* Ap = g_q + (size_t)b * CH * HW + (size_t)(it * 128) * CH;
        const bf16* Bp = g_k + (size_t)b * CH * HW + (size_t)(jt * 128) * CH;
        gemm_body<5>(Ap, Bp, CH, HW, it * 128, jt * 128, 0.0625f,
                     g_s + (size_t)b * HW * HW, nullptr, nullptr, g_l + b * HW);
    }
}

// ---------------- attn + proj fused (counter-chained, small spin set) ------------
// bids 0..255: attn (b=bid>>6, it=(bid&63)>>1, ct=bid&1), bumps g_cnt[b][it].
// bids 256..511: proj, waits g_cnt[b][it]==2 (both attn c-tiles of its i-tile).
__global__ void __launch_bounds__(256, 2) attn_proj(
    float* __restrict__ out, const float* __restrict__ x,
    const float* __restrict__ bp)
{
    const int bid = blockIdx.x;
    const int tid = threadIdx.x;

    if (bid < 256) {
        const int b = bid >> 6, r = bid & 63, it = r >> 1, ct = r & 1;
        const bf16* Ap = g_s + (size_t)b * HW * HW + (size_t)(it * 128) * HW;
        const bf16* Bp = g_v + (size_t)b * CH * HW + (size_t)(ct * 128) * HW;
        gemm_body<6>(Ap, Bp, HW, CH, it * 128, ct * 128, 1.0f,
                     g_atT + (size_t)b * CH * HW, nullptr, nullptr, g_l + b * HW);
        __threadfence();
        __syncthreads();
        if (tid == 0) atomicAdd(&g_cnt[b * 32 + it], 1);
    } else {
        const int t = bid - 256, b = t >> 6, r = t & 63, it = r >> 1, ct = r & 1;
        if (tid == 0) {
            while (((volatile int*)g_cnt)[b * 32 + it] < 2) __nanosleep(128);
        }
        __syncthreads();
        const bf16* Ap = g_w16 + 3 * CH * CH + (size_t)(ct * 128) * CH;
        const bf16* Bp = g_atT + (size_t)b * CH * HW + (size_t)(it * 128) * CH;
        gemm_body<4>(Ap, Bp, CH, HW, ct * 128, it * 128, 1.0f,
                     out + (size_t)b * CH * HW, bp, x + (size_t)b * CH * HW, nullptr);
    }
}

// ---------------- launch --------------------------------------------------------
extern "C" void kernel_launch(void* const* d_in, const int* in_sizes, int n_in,
                              void* d_out, int out_size) {
    const float* x  = (const float*)d_in[0];
    const float* gs = (const float*)d_in[1];
    const float* gb = (const float*)d_in[2];
    const float* wq = (const float*)d_in[3];
    const float* bq = (const float*)d_in[4];
    const float* wk = (const float*)d_in[5];
    const float* bk = (const float*)d_in[6];
    const float* wv = (const float*)d_in[7];
    const float* bv = (const float*)d_in[8];
    const float* wp = (const float*)d_in[9];
    const float* bp = (const float*)d_in[10];
    float* out = (float*)d_out;

    cudaFuncSetAttribute(qk_kernel, cudaFuncAttributeMaxDynamicSharedMemorySize, GEMM_SMEM_BYTES);
    cudaFuncSetAttribute(scores_v,  cudaFuncAttributeMaxDynamicSharedMemorySize, GEMM_SMEM_BYTES);
    cudaFuncSetAttribute(attn_proj, cudaFuncAttributeMaxDynamicSharedMemorySize, GEMM_SMEM_BYTES);

    // 1) prep (stats slices + weight conv + zero l/counters) -> gn_apply_t
    prep<<<1280, 256>>>(x, wq, wk, wv, wp);
    gn_apply_t<<<dim3(HW / 32, CH / 64, BATCH), 256>>>(x, gs, gb);

    // 2) Q, K
    qk_kernel<<<dim3(4, HW / 128, BATCH), 256, GEMM_SMEM_BYTES>>>(bq, bk);

    // 3) V (independent bids) + scores/expS/row-sums in one launch
    scores_v<<<256 + 4096, 256, GEMM_SMEM_BYTES>>>(bv);

    // 4) attn + proj fused (proj waits per-i-tile counter)
    attn_proj<<<512, 256, GEMM_SMEM_BYTES>>>(out, x, bp);
}